// round 14
// baseline (speedup 1.0000x reference)
#include <cuda_runtime.h>

#define C6   6
#define NPTS 32768
#define LL   2048
#define NB   2
#define TOT  (NB*C6*NPTS)
#define LOG2E 1.4426950408889634f
#define QPB  222          // queries per block (148 blocks per batch)
#define GRID_B 296

// ---------------- device scratch (static, allocation-free) ----------------
// key-pair SoA: per pair j (keys 2j,2j+1), 12 floats:
// {k0e,k0o, k1e,k1o, k2e,k2o, v0e,v0o, v1e,v1o, v2e,v2o}
__device__ float4 g_kv[NB][3072];     // 48KB per batch
__device__ float  g_sp[16][60];       // stats partials: [0..5]=rs, [6..41]=ws, [42..59]=psum
__device__ float  g_pt[12][GRID_B];   // transposed BN partials [stat][block]
__device__ int    g_cnt;              // kB arrival counter (reset by kA)

// ---------------- helpers ----------------
__device__ __forceinline__ float ex2f(float x){ float r; asm("ex2.approx.ftz.f32 %0, %1;" : "=f"(r) : "f"(x)); return r; }
typedef unsigned long long u64;
__device__ __forceinline__ u64 pk2(float a, float b){ u64 r; asm("mov.b64 %0, {%1, %2};" : "=l"(r) : "f"(a), "f"(b)); return r; }
__device__ __forceinline__ void upk2(u64 v, float& a, float& b){ asm("mov.b64 {%0, %1}, %2;" : "=f"(a), "=f"(b) : "l"(v)); }
__device__ __forceinline__ u64 ffma2(u64 a, u64 b, u64 c){ u64 d; asm("fma.rn.f32x2 %0, %1, %2, %3;" : "=l"(d) : "l"(a), "l"(b), "l"(c)); return d; }
__device__ __forceinline__ u64 fmul2(u64 a, u64 b){ u64 d; asm("mul.rn.f32x2 %0, %1, %2;" : "=l"(d) : "l"(a), "l"(b)); return d; }
__device__ __forceinline__ u64 fadd2(u64 a, u64 b){ u64 d; asm("add.rn.f32x2 %0, %1, %2;" : "=l"(d) : "l"(a), "l"(b)); return d; }

// ============================================================================
// Kernel A: prep. Blocks 0..15 = stats partials over L-chunks of 128
// (additive: no-max softmax), one float4 iteration per warp;
// blocks 16..31 = per-(b,l) k/v_intra generation (256 keys each, 256 threads).
// Block 0 also resets the kB arrival counter (kA precedes kB every replay).
// ============================================================================
__global__ void __launch_bounds__(512) kA(
    const float* __restrict__ curves,
    const float* __restrict__ Watt,
    const float* __restrict__ Wpn,  const float* __restrict__ bpn,
    const float* __restrict__ Wb,   const float* __restrict__ Wbv)
{
    const int tid = threadIdx.x, wp = tid>>5, ln = tid&31;
    const int bid = blockIdx.x;
    float watt[6];
    #pragma unroll
    for (int c=0;c<6;c++) watt[c] = Watt[c];

    if (bid < 16) {
        if (bid == 0 && tid == 0) g_cnt = 0;       // reset kB handshake
        const int l0 = bid*128;
        if (wp < 6) {
            // row-softmax partials for row (b,k): rs = sum e, ws[c] = sum cv*e
            int b = wp/3, k = wp%3;
            const float* base = curves + (b*18 + k)*LL + l0;
            float rs = 0.f, ws[6] = {0,0,0,0,0,0};
            {
                int l = ln*4;
                float4 cv4[6];
                #pragma unroll
                for (int c=0;c<6;c++) cv4[c] = *(const float4*)(base + c*3*LL + l);
                #pragma unroll
                for (int u=0;u<4;u++){
                    float cvu[6], a = 0.f;
                    #pragma unroll
                    for (int c=0;c<6;c++){ cvu[c] = ((const float*)&cv4[c])[u]; a += cvu[c]*watt[c]; }
                    float e = ex2f(a*LOG2E);
                    rs += e;
                    #pragma unroll
                    for (int c=0;c<6;c++) ws[c] += cvu[c]*e;
                }
            }
            #pragma unroll
            for (int o=16;o;o>>=1){
                rs += __shfl_down_sync(0xffffffffu, rs, o);
                #pragma unroll
                for (int c=0;c<6;c++) ws[c] += __shfl_down_sync(0xffffffffu, ws[c], o);
            }
            if (ln==0){
                g_sp[bid][wp] = rs;
                #pragma unroll
                for (int c=0;c<6;c++) g_sp[bid][6 + wp*6 + c] = ws[c];
            }
        } else {
            // pmean partial sums: 18 rows, 10 warps, one float4 each
            for (int r = wp-6; r < 18; r += 10) {
                const float* p = curves + r*LL + l0;
                float4 v = *(const float4*)(p + ln*4);
                float s = v.x+v.y+v.z+v.w;
                #pragma unroll
                for (int o=16;o;o>>=1) s += __shfl_down_sync(0xffffffffu, s, o);
                if (ln==0) g_sp[bid][42 + r] = s;
            }
        }
        return;
    }

    // --- blocks 16..31: per (b,l) k_intra / v_intra, key-pair SoA layout ---
    if (tid >= 256) return;
    float wbar[3];
    #pragma unroll
    for (int k=0;k<3;k++) wbar[k] = (Wpn[k] + Wpn[3+k] + Wpn[6+k]) * (1.f/3.f);
    float bbar = (bpn[0]+bpn[1]+bpn[2]) * (1.f/3.f);
    float wb[18], wbv[18];
    #pragma unroll
    for (int i=0;i<18;i++){ wb[i]=Wb[i]; wbv[i]=Wbv[i]; }

    int idx = (bid-16)*256 + tid;                // < 4096
    int b = idx >> 11, l = idx & (LL-1);
    float cv[6][3];
    #pragma unroll
    for (int c=0;c<6;c++)
        #pragma unroll
        for (int k=0;k<3;k++)
            cv[c][k] = curves[((b*6+c)*3+k)*LL + l];
    float a0=0.f,a1=0.f,a2=0.f;
    #pragma unroll
    for (int c=0;c<6;c++){ a0+=cv[c][0]*watt[c]; a1+=cv[c][1]*watt[c]; a2+=cv[c][2]*watt[c]; }
    float mx = fmaxf(a0, fmaxf(a1,a2));
    float e0=ex2f((a0-mx)*LOG2E), e1=ex2f((a1-mx)*LOG2E), e2=ex2f((a2-mx)*LOG2E);
    float inv = 1.0f/(e0+e1+e2);
    float w0=e0*inv, w1=e1*inv, w2=e2*inv;
    float kk0=0,kk1=0,kk2=0, vv0=0,vv1=0,vv2=0;
    #pragma unroll
    for (int c=0;c<6;c++){
        float ci = cv[c][0]*w0 + cv[c][1]*w1 + cv[c][2]*w2;
        float pn;
        if (b==0) {
            pn = wbar[0]*cv[c][0]+wbar[1]*cv[c][1]+wbar[2]*cv[c][2]+bbar;
        } else {
            float p0 = curves[(c*3+0)*LL+l], p1 = curves[(c*3+1)*LL+l], p2 = curves[(c*3+2)*LL+l];
            pn = wbar[0]*p0+wbar[1]*p1+wbar[2]*p2+bbar;
        }
        float ga = ci + pn;
        kk0 += wb[0*6+c]*ga; kk1 += wb[1*6+c]*ga; kk2 += wb[2*6+c]*ga;
        vv0 += wbv[0*6+c]*ga; vv1 += wbv[1*6+c]*ga; vv2 += wbv[2*6+c]*ga;
    }
    // key-pair interleave: pair j = l>>1, slot e = l&1
    float* dst = (float*)&g_kv[b][0] + (l>>1)*12 + (l&1);
    dst[0]  = kk0; dst[2]  = kk1; dst[4]  = kk2;
    dst[6]  = vv0; dst[8]  = vv1; dst[10] = vv2;
}

// ============================================================================
// Kernel B: attention + full epilogue INCLUDING BatchNorm apply (grid-wide
// handshake; all 296 blocks are co-resident: 2 CTAs/SM x 148 SMs, enforced by
// __launch_bounds__(1024,2)). quarter = wid&3 (SMSP-balanced idle warps),
// q_local = (wid>>2)*32+lane (warp-uniform quarter -> pure LDS broadcast).
// Split-K partials combine additively (no-max softmax). After the per-block
// BN partial write: threadfence + atomic arrival; spin until all arrive;
// every block redundantly reduces g_pt (deterministic) and applies
// out = leakyrelu(x + BN(y)) for its own queries. No kernel C.
// ============================================================================
__global__ void __launch_bounds__(1024, 2) kB(
    const float* __restrict__ x,
    const float* __restrict__ Wc, const float* __restrict__ lng, const float* __restrict__ lnb,
    const float* __restrict__ Wd,
    const float* __restrict__ Wpl, const float* __restrict__ bpl,
    const float* __restrict__ Wa,  const float* __restrict__ Wav,
    const float* __restrict__ bng, const float* __restrict__ bnb,
    float* __restrict__ out)
{
    extern __shared__ float4 s_kv[];               // 3072 float4 = 48 KB
    __shared__ float4 s_part[QPB][3];              // quarter partials (~10.7 KB)
    __shared__ float s_red[32][12];
    __shared__ float s_tmp[60], s_cur[36], s_pl[18];
    __shared__ float s_wc[18], s_ki[9], s_vi[9], s_lng[6], s_lnb[6], s_wd[36];
    __shared__ float sm[12];
    __shared__ float2 s_st[6];
    const int tid = threadIdx.x;
    const int bb = (blockIdx.x >= 148) ? 1 : 0;
    const int blk = blockIdx.x - bb*148;
    const int start = blk*QPB;
    const int len = min(QPB, NPTS - start);

    const float4* src = &g_kv[bb][0];
    #pragma unroll
    for (int i = 0; i < 3; i++) s_kv[tid + i*1024] = src[tid + i*1024];
    if (tid < 18) s_wc[tid] = Wc[tid] * (LOG2E * 0.57735026918962576f);  // fold log2e/sqrt(3)
    if (tid < 6) { s_lng[tid] = lng[tid]; s_lnb[tid] = lnb[tid]; }
    if (tid < 36) s_wd[tid] = Wd[tid];
    if (tid >= 64 && tid < 124) {                   // fold 16 partial blocks
        int t = tid - 64;
        float s = 0.f;
        #pragma unroll
        for (int p=0;p<16;p++) s += g_sp[p][t];
        s_tmp[t] = s;
    }
    __syncthreads();
    if (tid < 36) {                                 // curver[b][c][k]
        int b = tid/18, rem = tid%18, c = rem/3, k = rem%3;
        int row = b*3 + k;
        s_cur[tid] = s_tmp[6 + row*6 + c] / s_tmp[row];
    } else if (tid < 54) {                          // p_l[c][m]
        int t = tid-36, c = t/3, m = t%3;
        float v = bpl[m];
        #pragma unroll
        for (int k=0;k<3;k++) v += Wpl[m*3+k]*s_tmp[42+c*3+k]*(1.0f/LL);
        s_pl[t] = v;
    }
    __syncthreads();
    if (tid < 9) {                                  // k_inter[m*3+k] (gi folded in)
        int m = tid/3, k = tid%3;
        float v = 0.f;
        #pragma unroll
        for (int c=0;c<6;c++) v += Wa[m*6+c]*(s_cur[bb*18+c*3+k] + s_pl[c*3+k]);
        s_ki[tid] = v;
    } else if (tid < 18) {                          // v_inter[k*3+m]
        int t = tid-9, k = t/3, m = t%3;
        float v = 0.f;
        #pragma unroll
        for (int c=0;c<6;c++) v += Wav[m*6+c]*(s_cur[bb*18+c*3+k] + s_pl[c*3+k]);
        s_vi[t] = v;
    }
    __syncthreads();

    const int wid = tid>>5, lane = tid&31;
    const int quarter = wid & 3;                    // one idle warp per SMSP
    const int q_local = ((wid>>2)<<5) + lane;       // 0..255, warp-uniform quarter
    const bool active = (q_local < len);
    const int n = start + q_local;

    float q0=0.f,q1=0.f,q2=0.f;
    u64 a0=0,a1=0,a2=0,ls=0;
    if (active) {
        float xv[6];
        #pragma unroll
        for (int c=0;c<6;c++) xv[c] = x[(bb*6+c)*NPTS + n];
        q0 = xv[0]*s_wc[0]+xv[1]*s_wc[1]+xv[2]*s_wc[2]+xv[3]*s_wc[3]+xv[4]*s_wc[4]+xv[5]*s_wc[5];
        q1 = xv[0]*s_wc[6]+xv[1]*s_wc[7]+xv[2]*s_wc[8]+xv[3]*s_wc[9]+xv[4]*s_wc[10]+xv[5]*s_wc[11];
        q2 = xv[0]*s_wc[12]+xv[1]*s_wc[13]+xv[2]*s_wc[14]+xv[3]*s_wc[15]+xv[4]*s_wc[16]+xv[5]*s_wc[17];
        u64 qq0=pk2(q0,q0), qq1=pk2(q1,q1), qq2=pk2(q2,q2);

        const ulonglong2* kv2 = (const ulonglong2*)s_kv + quarter*768;   // 256 pairs
        #pragma unroll 2
        for (int j=0;j<256;j++){
            ulonglong2 t0 = kv2[3*j], t1 = kv2[3*j+1], t2 = kv2[3*j+2];
            u64 sA = ffma2(qq0, t0.x, ffma2(qq1, t0.y, fmul2(qq2, t1.x)));
            float s0,s1; upk2(sA,s0,s1);
            u64 pA = pk2(ex2f(s0), ex2f(s1));
            a0 = ffma2(pA, t1.y, a0); a1 = ffma2(pA, t2.x, a1);
            a2 = ffma2(pA, t2.y, a2); ls = fadd2(ls, pA);
        }
    }

    if (active && quarter > 0){
        float x0,x1,x2,x3,x4,x5,l0,l1;
        upk2(a0,x0,x1); upk2(a1,x2,x3); upk2(a2,x4,x5); upk2(ls,l0,l1);
        s_part[q_local][quarter-1] = make_float4(x0+x1, x2+x3, x4+x5, l0+l1);
    }
    __syncthreads();

    float ycache[6];
    float ts[6]={0,0,0,0,0,0}, tss[6]={0,0,0,0,0,0};
    const bool epi = active && (quarter == 0);
    if (epi){
        float x0,x1,x2,x3,x4,x5,l0,l1;
        upk2(a0,x0,x1); upk2(a1,x2,x3); upk2(a2,x4,x5); upk2(ls,l0,l1);
        float fa0 = x0+x1, fa1 = x2+x3, fa2 = x4+x5, lsum = l0+l1;
        #pragma unroll
        for (int p=0;p<3;p++){
            float4 pp = s_part[q_local][p];
            fa0 += pp.x; fa1 += pp.y; fa2 += pp.z; lsum += pp.w;
        }

        float rinv = 1.0f/lsum;
        float cf[6], e[3];
        #pragma unroll
        for (int k=0;k<3;k++)
            e[k] = ex2f(q0*s_ki[k] + q1*s_ki[3+k] + q2*s_ki[6+k]);
        float einv = 1.0f/(e[0]+e[1]+e[2]);
        #pragma unroll
        for (int m=0;m<3;m++)
            cf[m] = (e[0]*s_vi[m] + e[1]*s_vi[3+m] + e[2]*s_vi[6+m]) * einv;
        cf[3]=fa0*rinv; cf[4]=fa1*rinv; cf[5]=fa2*rinv;

        float mu = (cf[0]+cf[1]+cf[2]+cf[3]+cf[4]+cf[5]) * (1.f/6.f);
        float var = 0.f;
        #pragma unroll
        for (int j=0;j<6;j++){ float d=cf[j]-mu; var += d*d; }
        var *= (1.f/6.f);
        float istd = rsqrtf(var + 1e-5f);
        #pragma unroll
        for (int j=0;j<6;j++) cf[j] = (cf[j]-mu)*istd*s_lng[j] + s_lnb[j];
        #pragma unroll
        for (int o=0;o<6;o++){
            float y=0.f;
            #pragma unroll
            for (int j=0;j<6;j++) y += s_wd[o*6+j]*cf[j];
            ycache[o]=y; ts[o]=y; tss[o]=y*y;
        }
    }
    // deterministic block reduction of BN partials (non-epilogue threads add 0)
    #pragma unroll
    for (int j=0;j<6;j++){
        #pragma unroll
        for (int o=16;o;o>>=1){
            ts[j]  += __shfl_down_sync(0xffffffffu, ts[j],  o);
            tss[j] += __shfl_down_sync(0xffffffffu, tss[j], o);
        }
    }
    if (lane==0){
        #pragma unroll
        for (int j=0;j<6;j++){ s_red[wid][j]=ts[j]; s_red[wid][6+j]=tss[j]; }
    }
    __syncthreads();
    if (tid < 12){
        float s = 0.f;
        #pragma unroll
        for (int w=0;w<32;w++) s += s_red[w][tid];
        g_pt[tid][blockIdx.x] = s;                  // transposed layout
    }
    __threadfence();
    __syncthreads();
    if (tid == 0){
        atomicAdd(&g_cnt, 1);
        while (*(volatile int*)&g_cnt < GRID_B) { } // all 296 blocks co-resident
    }
    __syncthreads();
    __threadfence();

    // every block redundantly reduces the 12 x 296 partials (deterministic)
    if (wid < 12){
        float s = 0.f;
        for (int r = lane; r < GRID_B; r += 32) s += g_pt[wid][r];
        #pragma unroll
        for (int o=16;o;o>>=1) s += __shfl_down_sync(0xffffffffu, s, o);
        if (lane==0) sm[wid] = s;
    }
    __syncthreads();
    if (tid < 6){
        float mean = sm[tid]*(1.f/65536.f);
        float var  = sm[tid+6]*(1.f/65536.f) - mean*mean;
        float sc = bng[tid]*rsqrtf(var+1e-5f);
        s_st[tid] = make_float2(sc, bnb[tid]-mean*sc);
    }
    __syncthreads();

    // apply BN + residual + LeakyReLU for this block's queries
    if (epi){
        #pragma unroll
        for (int o=0;o<6;o++){
            float2 st = s_st[o];
            float xo = x[(bb*6+o)*NPTS + n];
            float r = xo + ycache[o]*st.x + st.y;
            out[(bb*6+o)*NPTS + n] = r >= 0.f ? r : 0.2f*r;
        }
    }
}

// ============================================================================
extern "C" void kernel_launch(void* const* d_in, const int* in_sizes, int n_in,
                              void* d_out, int out_size) {
    (void)in_sizes; (void)n_in; (void)out_size;
    const float* x      = (const float*)d_in[0];
    const float* curves = (const float*)d_in[1];
    const float* Wa     = (const float*)d_in[2];
    const float* Wav    = (const float*)d_in[3];
    const float* Wb     = (const float*)d_in[4];
    const float* Wbv    = (const float*)d_in[5];
    const float* Wc     = (const float*)d_in[6];
    const float* Wd     = (const float*)d_in[7];
    const float* bng    = (const float*)d_in[8];
    const float* bnb    = (const float*)d_in[9];
    const float* Watt   = (const float*)d_in[10];
    const float* lng    = (const float*)d_in[11];
    const float* lnb    = (const float*)d_in[12];
    const float* Wpl    = (const float*)d_in[13];
    const float* bpl    = (const float*)d_in[14];
    const float* Wpn    = (const float*)d_in[15];
    const float* bpn    = (const float*)d_in[16];

    cudaFuncSetAttribute(kB, cudaFuncAttributeMaxDynamicSharedMemorySize, 48*1024);

    kA<<<32, 512>>>(curves, Watt, Wpn, bpn, Wb, Wbv);
    kB<<<GRID_B, 1024, 48*1024>>>(x, Wc, lng, lnb, Wd, Wpl, bpl, Wa, Wav,
                                  bng, bnb, (float*)d_out);
}

// round 15
// speedup vs baseline: 1.0511x; 1.0511x over previous
#include <cuda_runtime.h>

#define C6   6
#define NPTS 32768
#define LL   2048
#define NB   2
#define TOT  (NB*C6*NPTS)
#define LOG2E 1.4426950408889634f
#define QPB  222          // queries per block (148 blocks per batch)
#define HQPB 111          // half of QPB: thread handles queries qp and qp+111
#define GRID_B 296

// ---------------- device scratch (static, allocation-free) ----------------
// key-pair SoA: per pair j (keys 2j,2j+1), 12 floats:
// {k0e,k0o, k1e,k1o, k2e,k2o, v0e,v0o, v1e,v1o, v2e,v2o}
__device__ float4 g_kv[NB][3072];     // 48KB per batch
__device__ float  g_sp[16][60];       // stats partials: [0..5]=rs, [6..41]=ws, [42..59]=psum
__device__ float4 g_y4[TOT/4];        // y [B,6,N]
__device__ float  g_part[GRID_B][12]; // per-block BN partials

// ---------------- helpers ----------------
__device__ __forceinline__ float ex2f(float x){ float r; asm("ex2.approx.ftz.f32 %0, %1;" : "=f"(r) : "f"(x)); return r; }
typedef unsigned long long u64;
__device__ __forceinline__ u64 pk2(float a, float b){ u64 r; asm("mov.b64 %0, {%1, %2};" : "=l"(r) : "f"(a), "f"(b)); return r; }
__device__ __forceinline__ void upk2(u64 v, float& a, float& b){ asm("mov.b64 {%0, %1}, %2;" : "=f"(a), "=f"(b) : "l"(v)); }
__device__ __forceinline__ u64 ffma2(u64 a, u64 b, u64 c){ u64 d; asm("fma.rn.f32x2 %0, %1, %2, %3;" : "=l"(d) : "l"(a), "l"(b), "l"(c)); return d; }
__device__ __forceinline__ u64 fmul2(u64 a, u64 b){ u64 d; asm("mul.rn.f32x2 %0, %1, %2;" : "=l"(d) : "l"(a), "l"(b)); return d; }
__device__ __forceinline__ u64 fadd2(u64 a, u64 b){ u64 d; asm("add.rn.f32x2 %0, %1, %2;" : "=l"(d) : "l"(a), "l"(b)); return d; }

// ============================================================================
// Kernel A: prep. Blocks 0..15 = stats partials over L-chunks of 128
// (additive: no-max softmax), one float4 iteration per warp;
// blocks 16..31 = per-(b,l) k/v_intra generation (256 keys each, 256 threads).
// ============================================================================
__global__ void __launch_bounds__(512) kA(
    const float* __restrict__ curves,
    const float* __restrict__ Watt,
    const float* __restrict__ Wpn,  const float* __restrict__ bpn,
    const float* __restrict__ Wb,   const float* __restrict__ Wbv)
{
    const int tid = threadIdx.x, wp = tid>>5, ln = tid&31;
    const int bid = blockIdx.x;
    float watt[6];
    #pragma unroll
    for (int c=0;c<6;c++) watt[c] = Watt[c];

    if (bid < 16) {
        const int l0 = bid*128;
        if (wp < 6) {
            int b = wp/3, k = wp%3;
            const float* base = curves + (b*18 + k)*LL + l0;
            float rs = 0.f, ws[6] = {0,0,0,0,0,0};
            {
                int l = ln*4;
                float4 cv4[6];
                #pragma unroll
                for (int c=0;c<6;c++) cv4[c] = *(const float4*)(base + c*3*LL + l);
                #pragma unroll
                for (int u=0;u<4;u++){
                    float cvu[6], a = 0.f;
                    #pragma unroll
                    for (int c=0;c<6;c++){ cvu[c] = ((const float*)&cv4[c])[u]; a += cvu[c]*watt[c]; }
                    float e = ex2f(a*LOG2E);
                    rs += e;
                    #pragma unroll
                    for (int c=0;c<6;c++) ws[c] += cvu[c]*e;
                }
            }
            #pragma unroll
            for (int o=16;o;o>>=1){
                rs += __shfl_down_sync(0xffffffffu, rs, o);
                #pragma unroll
                for (int c=0;c<6;c++) ws[c] += __shfl_down_sync(0xffffffffu, ws[c], o);
            }
            if (ln==0){
                g_sp[bid][wp] = rs;
                #pragma unroll
                for (int c=0;c<6;c++) g_sp[bid][6 + wp*6 + c] = ws[c];
            }
        } else {
            for (int r = wp-6; r < 18; r += 10) {
                const float* p = curves + r*LL + l0;
                float4 v = *(const float4*)(p + ln*4);
                float s = v.x+v.y+v.z+v.w;
                #pragma unroll
                for (int o=16;o;o>>=1) s += __shfl_down_sync(0xffffffffu, s, o);
                if (ln==0) g_sp[bid][42 + r] = s;
            }
        }
        return;
    }

    // --- blocks 16..31: per (b,l) k_intra / v_intra, key-pair SoA layout ---
    if (tid >= 256) return;
    float wbar[3];
    #pragma unroll
    for (int k=0;k<3;k++) wbar[k] = (Wpn[k] + Wpn[3+k] + Wpn[6+k]) * (1.f/3.f);
    float bbar = (bpn[0]+bpn[1]+bpn[2]) * (1.f/3.f);
    float wb[18], wbv[18];
    #pragma unroll
    for (int i=0;i<18;i++){ wb[i]=Wb[i]; wbv[i]=Wbv[i]; }

    int idx = (bid-16)*256 + tid;                // < 4096
    int b = idx >> 11, l = idx & (LL-1);
    float cv[6][3];
    #pragma unroll
    for (int c=0;c<6;c++)
        #pragma unroll
        for (int k=0;k<3;k++)
            cv[c][k] = curves[((b*6+c)*3+k)*LL + l];
    float a0=0.f,a1=0.f,a2=0.f;
    #pragma unroll
    for (int c=0;c<6;c++){ a0+=cv[c][0]*watt[c]; a1+=cv[c][1]*watt[c]; a2+=cv[c][2]*watt[c]; }
    float mx = fmaxf(a0, fmaxf(a1,a2));
    float e0=ex2f((a0-mx)*LOG2E), e1=ex2f((a1-mx)*LOG2E), e2=ex2f((a2-mx)*LOG2E);
    float inv = 1.0f/(e0+e1+e2);
    float w0=e0*inv, w1=e1*inv, w2=e2*inv;
    float kk0=0,kk1=0,kk2=0, vv0=0,vv1=0,vv2=0;
    #pragma unroll
    for (int c=0;c<6;c++){
        float ci = cv[c][0]*w0 + cv[c][1]*w1 + cv[c][2]*w2;
        float pn;
        if (b==0) {
            pn = wbar[0]*cv[c][0]+wbar[1]*cv[c][1]+wbar[2]*cv[c][2]+bbar;
        } else {
            float p0 = curves[(c*3+0)*LL+l], p1 = curves[(c*3+1)*LL+l], p2 = curves[(c*3+2)*LL+l];
            pn = wbar[0]*p0+wbar[1]*p1+wbar[2]*p2+bbar;
        }
        float ga = ci + pn;
        kk0 += wb[0*6+c]*ga; kk1 += wb[1*6+c]*ga; kk2 += wb[2*6+c]*ga;
        vv0 += wbv[0*6+c]*ga; vv1 += wbv[1*6+c]*ga; vv2 += wbv[2*6+c]*ga;
    }
    float* dst = (float*)&g_kv[b][0] + (l>>1)*12 + (l&1);
    dst[0]  = kk0; dst[2]  = kk1; dst[4]  = kk2;
    dst[6]  = vv0; dst[8]  = vv1; dst[10] = vv2;
}

// ============================================================================
// Kernel B: attention + epilogue. 296 blocks x 512 threads, 2 CTAs/SM.
// TWO queries per thread (n = start+qp and start+111+qp) share each key-pair
// load: 3 LDS.128 serve 4 products (halves L1 traffic vs 1 query/thread).
// quarter = wid&3 (SMSP-balanced partial warps), qp = (wid>>2)*32+lane
// (warp-uniform quarter -> pure LDS broadcast). Split-K partials combine
// additively (no-max softmax); quarter 0 does the epilogue.
// ============================================================================
__global__ void __launch_bounds__(512, 2) kB(
    const float* __restrict__ x,
    const float* __restrict__ Wc, const float* __restrict__ lng, const float* __restrict__ lnb,
    const float* __restrict__ Wd,
    const float* __restrict__ Wpl, const float* __restrict__ bpl,
    const float* __restrict__ Wa,  const float* __restrict__ Wav)
{
    extern __shared__ float4 s_kv[];               // 3072 float4 = 48 KB
    __shared__ float4 s_part[QPB][3];              // quarter partials (~10.7 KB)
    __shared__ float s_red[16][12];
    __shared__ float s_tmp[60], s_cur[36], s_pl[18];
    __shared__ float s_wc[18], s_ki[9], s_vi[9], s_lng[6], s_lnb[6], s_wd[36];
    const int tid = threadIdx.x;
    const int bb = (blockIdx.x >= 148) ? 1 : 0;
    const int blk = blockIdx.x - bb*148;
    const int start = blk*QPB;
    const int len = min(QPB, NPTS - start);

    const float4* src = &g_kv[bb][0];
    #pragma unroll
    for (int i = 0; i < 6; i++) s_kv[tid + i*512] = src[tid + i*512];
    if (tid < 18) s_wc[tid] = Wc[tid] * (LOG2E * 0.57735026918962576f);  // fold log2e/sqrt(3)
    if (tid < 6) { s_lng[tid] = lng[tid]; s_lnb[tid] = lnb[tid]; }
    if (tid < 36) s_wd[tid] = Wd[tid];
    if (tid >= 64 && tid < 124) {                   // fold 16 stats partials
        int t = tid - 64;
        float s = 0.f;
        #pragma unroll
        for (int p=0;p<16;p++) s += g_sp[p][t];
        s_tmp[t] = s;
    }
    __syncthreads();
    if (tid < 36) {                                 // curver[b][c][k]
        int b = tid/18, rem = tid%18, c = rem/3, k = rem%3;
        int row = b*3 + k;
        s_cur[tid] = s_tmp[6 + row*6 + c] / s_tmp[row];
    } else if (tid < 54) {                          // p_l[c][m]
        int t = tid-36, c = t/3, m = t%3;
        float v = bpl[m];
        #pragma unroll
        for (int k=0;k<3;k++) v += Wpl[m*3+k]*s_tmp[42+c*3+k]*(1.0f/LL);
        s_pl[t] = v;
    }
    __syncthreads();
    if (tid < 9) {                                  // k_inter[m*3+k] (gi folded)
        int m = tid/3, k = tid%3;
        float v = 0.f;
        #pragma unroll
        for (int c=0;c<6;c++) v += Wa[m*6+c]*(s_cur[bb*18+c*3+k] + s_pl[c*3+k]);
        s_ki[tid] = v;
    } else if (tid < 18) {                          // v_inter[k*3+m]
        int t = tid-9, k = t/3, m = t%3;
        float v = 0.f;
        #pragma unroll
        for (int c=0;c<6;c++) v += Wav[m*6+c]*(s_cur[bb*18+c*3+k] + s_pl[c*3+k]);
        s_vi[t] = v;
    }
    __syncthreads();

    const int wid = tid>>5, lane = tid&31;
    const int quarter = wid & 3;                    // partial warps: one per SMSP
    const int qp = ((wid>>2)<<5) + lane;            // 0..127
    const bool act0 = (qp < HQPB);                  // query n0 = start + qp
    const bool act1 = (qp < len - HQPB);            // query n1 = start + 111 + qp
    const int n0 = start + qp, n1 = start + HQPB + qp;

    float qA0=0.f,qA1=0.f,qA2=0.f, qB0=0.f,qB1=0.f,qB2=0.f;
    if (act0) {
        float xv[6];
        #pragma unroll
        for (int c=0;c<6;c++) xv[c] = x[(bb*6+c)*NPTS + n0];
        qA0 = xv[0]*s_wc[0]+xv[1]*s_wc[1]+xv[2]*s_wc[2]+xv[3]*s_wc[3]+xv[4]*s_wc[4]+xv[5]*s_wc[5];
        qA1 = xv[0]*s_wc[6]+xv[1]*s_wc[7]+xv[2]*s_wc[8]+xv[3]*s_wc[9]+xv[4]*s_wc[10]+xv[5]*s_wc[11];
        qA2 = xv[0]*s_wc[12]+xv[1]*s_wc[13]+xv[2]*s_wc[14]+xv[3]*s_wc[15]+xv[4]*s_wc[16]+xv[5]*s_wc[17];
    }
    if (act1) {
        float xv[6];
        #pragma unroll
        for (int c=0;c<6;c++) xv[c] = x[(bb*6+c)*NPTS + n1];
        qB0 = xv[0]*s_wc[0]+xv[1]*s_wc[1]+xv[2]*s_wc[2]+xv[3]*s_wc[3]+xv[4]*s_wc[4]+xv[5]*s_wc[5];
        qB1 = xv[0]*s_wc[6]+xv[1]*s_wc[7]+xv[2]*s_wc[8]+xv[3]*s_wc[9]+xv[4]*s_wc[10]+xv[5]*s_wc[11];
        qB2 = xv[0]*s_wc[12]+xv[1]*s_wc[13]+xv[2]*s_wc[14]+xv[3]*s_wc[15]+xv[4]*s_wc[16]+xv[5]*s_wc[17];
    }
    u64 qa0=pk2(qA0,qA0), qa1=pk2(qA1,qA1), qa2=pk2(qA2,qA2);
    u64 qb0=pk2(qB0,qB0), qb1=pk2(qB1,qB1), qb2=pk2(qB2,qB2);
    u64 aA0=0,aA1=0,aA2=0,lsA=0, aB0=0,aB1=0,aB2=0,lsB=0;

    const ulonglong2* kv2 = (const ulonglong2*)s_kv + quarter*768;   // 256 pairs
    #pragma unroll 2
    for (int j=0;j<256;j++){
        ulonglong2 t0 = kv2[3*j], t1 = kv2[3*j+1], t2 = kv2[3*j+2];
        u64 sA = ffma2(qa0, t0.x, ffma2(qa1, t0.y, fmul2(qa2, t1.x)));
        u64 sB = ffma2(qb0, t0.x, ffma2(qb1, t0.y, fmul2(qb2, t1.x)));
        float sa0,sa1,sb0,sb1; upk2(sA,sa0,sa1); upk2(sB,sb0,sb1);
        u64 pA = pk2(ex2f(sa0), ex2f(sa1));
        u64 pB = pk2(ex2f(sb0), ex2f(sb1));
        aA0 = ffma2(pA, t1.y, aA0); aA1 = ffma2(pA, t2.x, aA1);
        aA2 = ffma2(pA, t2.y, aA2); lsA = fadd2(lsA, pA);
        aB0 = ffma2(pB, t1.y, aB0); aB1 = ffma2(pB, t2.x, aB1);
        aB2 = ffma2(pB, t2.y, aB2); lsB = fadd2(lsB, pB);
    }

    if (quarter > 0){
        float x0,x1,x2,x3,x4,x5,l0,l1;
        if (act0){
            upk2(aA0,x0,x1); upk2(aA1,x2,x3); upk2(aA2,x4,x5); upk2(lsA,l0,l1);
            s_part[qp][quarter-1] = make_float4(x0+x1, x2+x3, x4+x5, l0+l1);
        }
        if (act1){
            upk2(aB0,x0,x1); upk2(aB1,x2,x3); upk2(aB2,x4,x5); upk2(lsB,l0,l1);
            s_part[HQPB+qp][quarter-1] = make_float4(x0+x1, x2+x3, x4+x5, l0+l1);
        }
    }
    __syncthreads();

    float ts[6]={0,0,0,0,0,0}, tss[6]={0,0,0,0,0,0};
    if (quarter == 0){
        #pragma unroll
        for (int i=0;i<2;i++){
            if (i==0 ? !act0 : !act1) continue;
            const int qloc = qp + i*HQPB;
            const int n = start + qloc;
            float x0,x1,x2,x3,x4,x5,l0,l1;
            if (i==0){ upk2(aA0,x0,x1); upk2(aA1,x2,x3); upk2(aA2,x4,x5); upk2(lsA,l0,l1); }
            else     { upk2(aB0,x0,x1); upk2(aB1,x2,x3); upk2(aB2,x4,x5); upk2(lsB,l0,l1); }
            float fa0 = x0+x1, fa1 = x2+x3, fa2 = x4+x5, lsum = l0+l1;
            #pragma unroll
            for (int p=0;p<3;p++){
                float4 pp = s_part[qloc][p];
                fa0 += pp.x; fa1 += pp.y; fa2 += pp.z; lsum += pp.w;
            }
            float g0 = (i==0)?qA0:qB0, g1 = (i==0)?qA1:qB1, g2 = (i==0)?qA2:qB2;

            float rinv = 1.0f/lsum;
            float cf[6], e[3];
            #pragma unroll
            for (int k=0;k<3;k++)
                e[k] = ex2f(g0*s_ki[k] + g1*s_ki[3+k] + g2*s_ki[6+k]);
            float einv = 1.0f/(e[0]+e[1]+e[2]);
            #pragma unroll
            for (int m=0;m<3;m++)
                cf[m] = (e[0]*s_vi[m] + e[1]*s_vi[3+m] + e[2]*s_vi[6+m]) * einv;
            cf[3]=fa0*rinv; cf[4]=fa1*rinv; cf[5]=fa2*rinv;

            float mu = (cf[0]+cf[1]+cf[2]+cf[3]+cf[4]+cf[5]) * (1.f/6.f);
            float var = 0.f;
            #pragma unroll
            for (int j=0;j<6;j++){ float d=cf[j]-mu; var += d*d; }
            var *= (1.f/6.f);
            float istd = rsqrtf(var + 1e-5f);
            #pragma unroll
            for (int j=0;j<6;j++) cf[j] = (cf[j]-mu)*istd*s_lng[j] + s_lnb[j];
            #pragma unroll
            for (int o=0;o<6;o++){
                float y=0.f;
                #pragma unroll
                for (int j=0;j<6;j++) y += s_wd[o*6+j]*cf[j];
                ((float*)g_y4)[(bb*6+o)*NPTS + n] = y;
                ts[o]+=y; tss[o]+=y*y;
            }
        }
    }
    // deterministic block reduction of BN partials (non-epilogue threads add 0)
    #pragma unroll
    for (int j=0;j<6;j++){
        #pragma unroll
        for (int o=16;o;o>>=1){
            ts[j]  += __shfl_down_sync(0xffffffffu, ts[j],  o);
            tss[j] += __shfl_down_sync(0xffffffffu, tss[j], o);
        }
    }
    if (lane==0){
        #pragma unroll
        for (int j=0;j<6;j++){ s_red[wid][j]=ts[j]; s_red[wid][6+j]=tss[j]; }
    }
    __syncthreads();
    if (tid < 12){
        float s = 0.f;
        #pragma unroll
        for (int w=0;w<16;w++) s += s_red[w][tid];
        g_part[blockIdx.x][tid] = s;
    }
}

// ============================================================================
// Kernel C: BN stats (redundant per block, deterministic) + apply:
// out = leakyrelu(x + BN(y)). 256 blocks x 384 threads, 1 float4/thread.
// ============================================================================
__global__ void __launch_bounds__(384) kC(
    const float* __restrict__ x, const float* __restrict__ bng,
    const float* __restrict__ bnb, float* __restrict__ out)
{
    __shared__ float sm[12];
    __shared__ float2 s_st[6];
    const int tid = threadIdx.x, wp = tid>>5, ln = tid&31;

    // phase 1: every block reduces g_part[296][12] (12 warps, lane-strided)
    {
        float s = 0.f;
        for (int r = ln; r < GRID_B; r += 32) s += g_part[r][wp];
        #pragma unroll
        for (int o=16;o;o>>=1) s += __shfl_down_sync(0xffffffffu, s, o);
        if (ln==0) sm[wp] = s;
    }
    __syncthreads();
    if (tid < 6){
        float mean = sm[tid]*(1.f/65536.f);
        float var  = sm[tid+6]*(1.f/65536.f) - mean*mean;
        float sc = bng[tid]*rsqrtf(var+1e-5f);
        s_st[tid] = make_float2(sc, bnb[tid]-mean*sc);
    }
    __syncthreads();

    // phase 2: apply
    int idx = blockIdx.x*384 + tid;                  // 256*384 = 98304 exactly
    float4 xv = ((const float4*)x)[idx];
    float4 yv = g_y4[idx];
    int o = (idx >> 13) % 6;                         // 8192 float4 per (b,o) row
    float2 st = s_st[o];
    float4 r;
    r.x = xv.x + yv.x*st.x + st.y;
    r.y = xv.y + yv.y*st.x + st.y;
    r.z = xv.z + yv.z*st.x + st.y;
    r.w = xv.w + yv.w*st.x + st.y;
    r.x = r.x >= 0.f ? r.x : 0.2f*r.x;
    r.y = r.y >= 0.f ? r.y : 0.2f*r.y;
    r.z = r.z >= 0.f ? r.z : 0.2f*r.z;
    r.w = r.w >= 0.f ? r.w : 0.2f*r.w;
    ((float4*)out)[idx] = r;
}

// ============================================================================
extern "C" void kernel_launch(void* const* d_in, const int* in_sizes, int n_in,
                              void* d_out, int out_size) {
    (void)in_sizes; (void)n_in; (void)out_size;
    const float* x      = (const float*)d_in[0];
    const float* curves = (const float*)d_in[1];
    const float* Wa     = (const float*)d_in[2];
    const float* Wav    = (const float*)d_in[3];
    const float* Wb     = (const float*)d_in[4];
    const float* Wbv    = (const float*)d_in[5];
    const float* Wc     = (const float*)d_in[6];
    const float* Wd     = (const float*)d_in[7];
    const float* bng    = (const float*)d_in[8];
    const float* bnb    = (const float*)d_in[9];
    const float* Watt   = (const float*)d_in[10];
    const float* lng    = (const float*)d_in[11];
    const float* lnb    = (const float*)d_in[12];
    const float* Wpl    = (const float*)d_in[13];
    const float* bpl    = (const float*)d_in[14];
    const float* Wpn    = (const float*)d_in[15];
    const float* bpn    = (const float*)d_in[16];

    cudaFuncSetAttribute(kB, cudaFuncAttributeMaxDynamicSharedMemorySize, 48*1024);

    kA<<<32, 512>>>(curves, Watt, Wpn, bpn, Wb, Wbv);
    kB<<<GRID_B, 512, 48*1024>>>(x, Wc, lng, lnb, Wd, Wpl, bpl, Wa, Wav);
    kC<<<256, 384>>>(x, bng, bnb, (float*)d_out);
}

// round 16
// speedup vs baseline: 1.0892x; 1.0363x over previous
#include <cuda_runtime.h>

#define C6   6
#define NPTS 32768
#define LL   2048
#define NB   2
#define TOT  (NB*C6*NPTS)
#define LOG2E 1.4426950408889634f
#define QPB  222          // queries per block (148 blocks per batch)
#define GRID_B 296

// ---------------- device scratch (static, allocation-free) ----------------
// key-pair SoA: per pair j (keys 2j,2j+1), 12 floats:
// {k0e,k0o, k1e,k1o, k2e,k2o, v0e,v0o, v1e,v1o, v2e,v2o}
__device__ float4 g_kv[NB][3072];     // 48KB per batch
__device__ float  g_sp[16][60];       // stats partials: [0..5]=rs, [6..41]=ws, [42..59]=psum
__device__ float4 g_y4[TOT/4];        // y [B,6,N]
__device__ float  g_part[GRID_B][12]; // per-block BN partials

// ---------------- helpers ----------------
__device__ __forceinline__ float ex2f(float x){ float r; asm("ex2.approx.ftz.f32 %0, %1;" : "=f"(r) : "f"(x)); return r; }
typedef unsigned long long u64;
__device__ __forceinline__ u64 pk2(float a, float b){ u64 r; asm("mov.b64 %0, {%1, %2};" : "=l"(r) : "f"(a), "f"(b)); return r; }
__device__ __forceinline__ void upk2(u64 v, float& a, float& b){ asm("mov.b64 {%0, %1}, %2;" : "=f"(a), "=f"(b) : "l"(v)); }
__device__ __forceinline__ u64 ffma2(u64 a, u64 b, u64 c){ u64 d; asm("fma.rn.f32x2 %0, %1, %2, %3;" : "=l"(d) : "l"(a), "l"(b), "l"(c)); return d; }
__device__ __forceinline__ u64 fmul2(u64 a, u64 b){ u64 d; asm("mul.rn.f32x2 %0, %1, %2;" : "=l"(d) : "l"(a), "l"(b)); return d; }
__device__ __forceinline__ u64 fadd2(u64 a, u64 b){ u64 d; asm("add.rn.f32x2 %0, %1, %2;" : "=l"(d) : "l"(a), "l"(b)); return d; }

// ============================================================================
// Kernel A: prep. Blocks 0..15 = stats partials over L-chunks of 128
// (additive: no-max softmax), one float4 iteration per warp;
// blocks 16..31 = per-(b,l) k/v_intra generation (256 keys each, 256 threads).
// ============================================================================
__global__ void __launch_bounds__(512) kA(
    const float* __restrict__ curves,
    const float* __restrict__ Watt,
    const float* __restrict__ Wpn,  const float* __restrict__ bpn,
    const float* __restrict__ Wb,   const float* __restrict__ Wbv)
{
    const int tid = threadIdx.x, wp = tid>>5, ln = tid&31;
    const int bid = blockIdx.x;
    float watt[6];
    #pragma unroll
    for (int c=0;c<6;c++) watt[c] = Watt[c];

    if (bid < 16) {
        const int l0 = bid*128;
        if (wp < 6) {
            int b = wp/3, k = wp%3;
            const float* base = curves + (b*18 + k)*LL + l0;
            float rs = 0.f, ws[6] = {0,0,0,0,0,0};
            {
                int l = ln*4;
                float4 cv4[6];
                #pragma unroll
                for (int c=0;c<6;c++) cv4[c] = *(const float4*)(base + c*3*LL + l);
                #pragma unroll
                for (int u=0;u<4;u++){
                    float cvu[6], a = 0.f;
                    #pragma unroll
                    for (int c=0;c<6;c++){ cvu[c] = ((const float*)&cv4[c])[u]; a += cvu[c]*watt[c]; }
                    float e = ex2f(a*LOG2E);
                    rs += e;
                    #pragma unroll
                    for (int c=0;c<6;c++) ws[c] += cvu[c]*e;
                }
            }
            #pragma unroll
            for (int o=16;o;o>>=1){
                rs += __shfl_down_sync(0xffffffffu, rs, o);
                #pragma unroll
                for (int c=0;c<6;c++) ws[c] += __shfl_down_sync(0xffffffffu, ws[c], o);
            }
            if (ln==0){
                g_sp[bid][wp] = rs;
                #pragma unroll
                for (int c=0;c<6;c++) g_sp[bid][6 + wp*6 + c] = ws[c];
            }
        } else {
            for (int r = wp-6; r < 18; r += 10) {
                const float* p = curves + r*LL + l0;
                float4 v = *(const float4*)(p + ln*4);
                float s = v.x+v.y+v.z+v.w;
                #pragma unroll
                for (int o=16;o;o>>=1) s += __shfl_down_sync(0xffffffffu, s, o);
                if (ln==0) g_sp[bid][42 + r] = s;
            }
        }
        return;
    }

    // --- blocks 16..31: per (b,l) k_intra / v_intra, key-pair SoA layout ---
    if (tid >= 256) return;
    float wbar[3];
    #pragma unroll
    for (int k=0;k<3;k++) wbar[k] = (Wpn[k] + Wpn[3+k] + Wpn[6+k]) * (1.f/3.f);
    float bbar = (bpn[0]+bpn[1]+bpn[2]) * (1.f/3.f);
    float wb[18], wbv[18];
    #pragma unroll
    for (int i=0;i<18;i++){ wb[i]=Wb[i]; wbv[i]=Wbv[i]; }

    int idx = (bid-16)*256 + tid;                // < 4096
    int b = idx >> 11, l = idx & (LL-1);
    float cv[6][3];
    #pragma unroll
    for (int c=0;c<6;c++)
        #pragma unroll
        for (int k=0;k<3;k++)
            cv[c][k] = curves[((b*6+c)*3+k)*LL + l];
    float a0=0.f,a1=0.f,a2=0.f;
    #pragma unroll
    for (int c=0;c<6;c++){ a0+=cv[c][0]*watt[c]; a1+=cv[c][1]*watt[c]; a2+=cv[c][2]*watt[c]; }
    float mx = fmaxf(a0, fmaxf(a1,a2));
    float e0=ex2f((a0-mx)*LOG2E), e1=ex2f((a1-mx)*LOG2E), e2=ex2f((a2-mx)*LOG2E);
    float inv = 1.0f/(e0+e1+e2);
    float w0=e0*inv, w1=e1*inv, w2=e2*inv;
    float kk0=0,kk1=0,kk2=0, vv0=0,vv1=0,vv2=0;
    #pragma unroll
    for (int c=0;c<6;c++){
        float ci = cv[c][0]*w0 + cv[c][1]*w1 + cv[c][2]*w2;
        float pn;
        if (b==0) {
            pn = wbar[0]*cv[c][0]+wbar[1]*cv[c][1]+wbar[2]*cv[c][2]+bbar;
        } else {
            float p0 = curves[(c*3+0)*LL+l], p1 = curves[(c*3+1)*LL+l], p2 = curves[(c*3+2)*LL+l];
            pn = wbar[0]*p0+wbar[1]*p1+wbar[2]*p2+bbar;
        }
        float ga = ci + pn;
        kk0 += wb[0*6+c]*ga; kk1 += wb[1*6+c]*ga; kk2 += wb[2*6+c]*ga;
        vv0 += wbv[0*6+c]*ga; vv1 += wbv[1*6+c]*ga; vv2 += wbv[2*6+c]*ga;
    }
    float* dst = (float*)&g_kv[b][0] + (l>>1)*12 + (l&1);
    dst[0]  = kk0; dst[2]  = kk1; dst[4]  = kk2;
    dst[6]  = vv0; dst[8]  = vv1; dst[10] = vv2;
}

// ============================================================================
// Kernel B: attention + epilogue. 296 blocks x 256 threads, 2 CTAs/SM.
// FOUR queries per thread (qp, qp+64, qp+128, qp+192) share each key-pair
// load: 3 LDS.128 serve 8 products. quarter = wid&3 (each SMSP owns one
// quarter, 2 warps x 2 CTAs = 4 warps/SMSP, perfectly balanced);
// qp = (wid>>2)*32+lane in 0..63 (warp-uniform quarter -> LDS broadcast).
// Split-K partials combine additively (no-max softmax); quarter 0 epilogue.
// ============================================================================
__global__ void __launch_bounds__(256, 2) kB(
    const float* __restrict__ x,
    const float* __restrict__ Wc, const float* __restrict__ lng, const float* __restrict__ lnb,
    const float* __restrict__ Wd,
    const float* __restrict__ Wpl, const float* __restrict__ bpl,
    const float* __restrict__ Wa,  const float* __restrict__ Wav)
{
    extern __shared__ float4 s_kv[];               // 3072 float4 = 48 KB
    __shared__ float4 s_part[QPB][3];              // quarter partials (~10.7 KB)
    __shared__ float s_red[8][12];
    __shared__ float s_tmp[60], s_cur[36], s_pl[18];
    __shared__ float s_wc[18], s_ki[9], s_vi[9], s_lng[6], s_lnb[6], s_wd[36];
    const int tid = threadIdx.x;
    const int bb = (blockIdx.x >= 148) ? 1 : 0;
    const int blk = blockIdx.x - bb*148;
    const int start = blk*QPB;
    const int len = min(QPB, NPTS - start);

    const float4* src = &g_kv[bb][0];
    #pragma unroll
    for (int i = 0; i < 12; i++) s_kv[tid + i*256] = src[tid + i*256];
    if (tid < 18) s_wc[tid] = Wc[tid] * (LOG2E * 0.57735026918962576f);  // fold log2e/sqrt(3)
    if (tid < 6) { s_lng[tid] = lng[tid]; s_lnb[tid] = lnb[tid]; }
    if (tid < 36) s_wd[tid] = Wd[tid];
    if (tid >= 64 && tid < 124) {                   // fold 16 stats partials
        int t = tid - 64;
        float s = 0.f;
        #pragma unroll
        for (int p=0;p<16;p++) s += g_sp[p][t];
        s_tmp[t] = s;
    }
    __syncthreads();
    if (tid < 36) {                                 // curver[b][c][k]
        int b = tid/18, rem = tid%18, c = rem/3, k = rem%3;
        int row = b*3 + k;
        s_cur[tid] = s_tmp[6 + row*6 + c] / s_tmp[row];
    } else if (tid < 54) {                          // p_l[c][m]
        int t = tid-36, c = t/3, m = t%3;
        float v = bpl[m];
        #pragma unroll
        for (int k=0;k<3;k++) v += Wpl[m*3+k]*s_tmp[42+c*3+k]*(1.0f/LL);
        s_pl[t] = v;
    }
    __syncthreads();
    if (tid < 9) {                                  // k_inter[m*3+k] (gi folded)
        int m = tid/3, k = tid%3;
        float v = 0.f;
        #pragma unroll
        for (int c=0;c<6;c++) v += Wa[m*6+c]*(s_cur[bb*18+c*3+k] + s_pl[c*3+k]);
        s_ki[tid] = v;
    } else if (tid < 18) {                          // v_inter[k*3+m]
        int t = tid-9, k = t/3, m = t%3;
        float v = 0.f;
        #pragma unroll
        for (int c=0;c<6;c++) v += Wav[m*6+c]*(s_cur[bb*18+c*3+k] + s_pl[c*3+k]);
        s_vi[t] = v;
    }
    __syncthreads();

    const int wid = tid>>5, lane = tid&31;
    const int quarter = wid & 3;                    // SMSP == quarter (balanced)
    const int qp = ((wid>>2)<<5) + lane;            // 0..63
    bool act[4];
    #pragma unroll
    for (int i=0;i<4;i++) act[i] = (qp + 64*i) < len;

    // build 4 packed queries (inactive -> 0)
    float qs[4][3];
    #pragma unroll
    for (int i=0;i<4;i++){
        qs[i][0]=qs[i][1]=qs[i][2]=0.f;
        if (act[i]){
            const int n = start + qp + 64*i;
            float xv[6];
            #pragma unroll
            for (int c=0;c<6;c++) xv[c] = x[(bb*6+c)*NPTS + n];
            qs[i][0] = xv[0]*s_wc[0]+xv[1]*s_wc[1]+xv[2]*s_wc[2]+xv[3]*s_wc[3]+xv[4]*s_wc[4]+xv[5]*s_wc[5];
            qs[i][1] = xv[0]*s_wc[6]+xv[1]*s_wc[7]+xv[2]*s_wc[8]+xv[3]*s_wc[9]+xv[4]*s_wc[10]+xv[5]*s_wc[11];
            qs[i][2] = xv[0]*s_wc[12]+xv[1]*s_wc[13]+xv[2]*s_wc[14]+xv[3]*s_wc[15]+xv[4]*s_wc[16]+xv[5]*s_wc[17];
        }
    }
    u64 qq[4][3];
    #pragma unroll
    for (int i=0;i<4;i++)
        #pragma unroll
        for (int m=0;m<3;m++) qq[i][m] = pk2(qs[i][m], qs[i][m]);
    u64 acc[4][3] = {{0,0,0},{0,0,0},{0,0,0},{0,0,0}};
    u64 lsm[4] = {0,0,0,0};

    const ulonglong2* kv2 = (const ulonglong2*)s_kv + quarter*768;   // 256 pairs
    #pragma unroll 2
    for (int j=0;j<256;j++){
        ulonglong2 t0 = kv2[3*j], t1 = kv2[3*j+1], t2 = kv2[3*j+2];
        #pragma unroll
        for (int i=0;i<4;i++){
            u64 s = ffma2(qq[i][0], t0.x, ffma2(qq[i][1], t0.y, fmul2(qq[i][2], t1.x)));
            float s0,s1; upk2(s,s0,s1);
            u64 p = pk2(ex2f(s0), ex2f(s1));
            acc[i][0] = ffma2(p, t1.y, acc[i][0]);
            acc[i][1] = ffma2(p, t2.x, acc[i][1]);
            acc[i][2] = ffma2(p, t2.y, acc[i][2]);
            lsm[i] = fadd2(lsm[i], p);
        }
    }

    if (quarter > 0){
        #pragma unroll
        for (int i=0;i<4;i++){
            if (act[i]){
                float x0,x1,x2,x3,x4,x5,l0,l1;
                upk2(acc[i][0],x0,x1); upk2(acc[i][1],x2,x3); upk2(acc[i][2],x4,x5); upk2(lsm[i],l0,l1);
                s_part[qp + 64*i][quarter-1] = make_float4(x0+x1, x2+x3, x4+x5, l0+l1);
            }
        }
    }
    __syncthreads();

    float ts[6]={0,0,0,0,0,0}, tss[6]={0,0,0,0,0,0};
    if (quarter == 0){
        #pragma unroll
        for (int i=0;i<4;i++){
            if (!act[i]) continue;
            const int qloc = qp + 64*i;
            const int n = start + qloc;
            float x0,x1,x2,x3,x4,x5,l0,l1;
            upk2(acc[i][0],x0,x1); upk2(acc[i][1],x2,x3); upk2(acc[i][2],x4,x5); upk2(lsm[i],l0,l1);
            float fa0 = x0+x1, fa1 = x2+x3, fa2 = x4+x5, lsum = l0+l1;
            #pragma unroll
            for (int p=0;p<3;p++){
                float4 pp = s_part[qloc][p];
                fa0 += pp.x; fa1 += pp.y; fa2 += pp.z; lsum += pp.w;
            }
            float g0 = qs[i][0], g1 = qs[i][1], g2 = qs[i][2];

            float rinv = 1.0f/lsum;
            float cf[6], e[3];
            #pragma unroll
            for (int k=0;k<3;k++)
                e[k] = ex2f(g0*s_ki[k] + g1*s_ki[3+k] + g2*s_ki[6+k]);
            float einv = 1.0f/(e[0]+e[1]+e[2]);
            #pragma unroll
            for (int m=0;m<3;m++)
                cf[m] = (e[0]*s_vi[m] + e[1]*s_vi[3+m] + e[2]*s_vi[6+m]) * einv;
            cf[3]=fa0*rinv; cf[4]=fa1*rinv; cf[5]=fa2*rinv;

            float mu = (cf[0]+cf[1]+cf[2]+cf[3]+cf[4]+cf[5]) * (1.f/6.f);
            float var = 0.f;
            #pragma unroll
            for (int j=0;j<6;j++){ float d=cf[j]-mu; var += d*d; }
            var *= (1.f/6.f);
            float istd = rsqrtf(var + 1e-5f);
            #pragma unroll
            for (int j=0;j<6;j++) cf[j] = (cf[j]-mu)*istd*s_lng[j] + s_lnb[j];
            #pragma unroll
            for (int o=0;o<6;o++){
                float y=0.f;
                #pragma unroll
                for (int j=0;j<6;j++) y += s_wd[o*6+j]*cf[j];
                ((float*)g_y4)[(bb*6+o)*NPTS + n] = y;
                ts[o]+=y; tss[o]+=y*y;
            }
        }
    }
    // deterministic block reduction of BN partials (non-epilogue threads add 0)
    #pragma unroll
    for (int j=0;j<6;j++){
        #pragma unroll
        for (int o=16;o;o>>=1){
            ts[j]  += __shfl_down_sync(0xffffffffu, ts[j],  o);
            tss[j] += __shfl_down_sync(0xffffffffu, tss[j], o);
        }
    }
    if (lane==0){
        #pragma unroll
        for (int j=0;j<6;j++){ s_red[wid][j]=ts[j]; s_red[wid][6+j]=tss[j]; }
    }
    __syncthreads();
    if (tid < 12){
        float s = 0.f;
        #pragma unroll
        for (int w=0;w<8;w++) s += s_red[w][tid];
        g_part[blockIdx.x][tid] = s;
    }
}

// ============================================================================
// Kernel C: BN stats (redundant per block, deterministic) + apply:
// out = leakyrelu(x + BN(y)). 256 blocks x 384 threads, 1 float4/thread.
// ============================================================================
__global__ void __launch_bounds__(384) kC(
    const float* __restrict__ x, const float* __restrict__ bng,
    const float* __restrict__ bnb, float* __restrict__ out)
{
    __shared__ float sm[12];
    __shared__ float2 s_st[6];
    const int tid = threadIdx.x, wp = tid>>5, ln = tid&31;

    // phase 1: every block reduces g_part[296][12] (12 warps, lane-strided)
    {
        float s = 0.f;
        for (int r = ln; r < GRID_B; r += 32) s += g_part[r][wp];
        #pragma unroll
        for (int o=16;o;o>>=1) s += __shfl_down_sync(0xffffffffu, s, o);
        if (ln==0) sm[wp] = s;
    }
    __syncthreads();
    if (tid < 6){
        float mean = sm[tid]*(1.f/65536.f);
        float var  = sm[tid+6]*(1.f/65536.f) - mean*mean;
        float sc = bng[tid]*rsqrtf(var+1e-5f);
        s_st[tid] = make_float2(sc, bnb[tid]-mean*sc);
    }
    __syncthreads();

    // phase 2: apply
    int idx = blockIdx.x*384 + tid;                  // 256*384 = 98304 exactly
    float4 xv = ((const float4*)x)[idx];
    float4 yv = g_y4[idx];
    int o = (idx >> 13) % 6;                         // 8192 float4 per (b,o) row
    float2 st = s_st[o];
    float4 r;
    r.x = xv.x + yv.x*st.x + st.y;
    r.y = xv.y + yv.y*st.x + st.y;
    r.z = xv.z + yv.z*st.x + st.y;
    r.w = xv.w + yv.w*st.x + st.y;
    r.x = r.x >= 0.f ? r.x : 0.2f*r.x;
    r.y = r.y >= 0.f ? r.y : 0.2f*r.y;
    r.z = r.z >= 0.f ? r.z : 0.2f*r.z;
    r.w = r.w >= 0.f ? r.w : 0.2f*r.w;
    ((float4*)out)[idx] = r;
}

// ============================================================================
extern "C" void kernel_launch(void* const* d_in, const int* in_sizes, int n_in,
                              void* d_out, int out_size) {
    (void)in_sizes; (void)n_in; (void)out_size;
    const float* x      = (const float*)d_in[0];
    const float* curves = (const float*)d_in[1];
    const float* Wa     = (const float*)d_in[2];
    const float* Wav    = (const float*)d_in[3];
    const float* Wb     = (const float*)d_in[4];
    const float* Wbv    = (const float*)d_in[5];
    const float* Wc     = (const float*)d_in[6];
    const float* Wd     = (const float*)d_in[7];
    const float* bng    = (const float*)d_in[8];
    const float* bnb    = (const float*)d_in[9];
    const float* Watt   = (const float*)d_in[10];
    const float* lng    = (const float*)d_in[11];
    const float* lnb    = (const float*)d_in[12];
    const float* Wpl    = (const float*)d_in[13];
    const float* bpl    = (const float*)d_in[14];
    const float* Wpn    = (const float*)d_in[15];
    const float* bpn    = (const float*)d_in[16];

    cudaFuncSetAttribute(kB, cudaFuncAttributeMaxDynamicSharedMemorySize, 48*1024);

    kA<<<32, 512>>>(curves, Watt, Wpn, bpn, Wb, Wbv);
    kB<<<GRID_B, 256, 48*1024>>>(x, Wc, lng, lnb, Wd, Wpl, bpl, Wa, Wav);
    kC<<<256, 384>>>(x, bng, bnb, (float*)d_out);
}